// round 15
// baseline (speedup 1.0000x reference)
#include <cuda_runtime.h>
#include <cuda_fp16.h>
#include <math.h>
#include <stdint.h>

#define Nn      8192
#define NFEATC  512
#define NHID    256
#define NCLASS  16
#define MAXDEG  160
#define ALPHAC  0.01f
#define CATW    (NHID + NCLASS)   /* 272 */

/* ---------------- device scratch ---------------- */
__device__ int    g_col[Nn * MAXDEG];
__device__ int    g_cnt[Nn];
__device__ float  g_XW[Nn * NHID];
__device__ float  g_h1[Nn * NHID];
__device__ float  g_Wh32[Nn * NHID];
__device__ __half g_Whh[Nn * NHID];
__device__ float  g_f1[Nn];
__device__ float  g_f2[Nn];
__device__ float  g_aW3[Nn * NCLASS];

/* ------ K1: CSR build, thread t owns cols [32t,32t+32), ONE block scan --- */
__global__ __launch_bounds__(256) void build_csr(const int4* __restrict__ adj4) {
    const int row = blockIdx.x, tid = threadIdx.x;
    const int lane = tid & 31, wid = tid >> 5;
    __shared__ __align__(16) int s_w[8];
    int4 v[8];
    const int4* base = adj4 + (size_t)row * (Nn / 4) + tid * 8;
#pragma unroll
    for (int i = 0; i < 8; i++) v[i] = base[i];           /* MLP = 8 */
    int cntl = 0;
#pragma unroll
    for (int i = 0; i < 8; i++)
        cntl += (v[i].x != 0) + (v[i].y != 0) + (v[i].z != 0) + (v[i].w != 0);
    int excl = cntl;
#pragma unroll
    for (int o = 1; o < 32; o <<= 1) {
        int t = __shfl_up_sync(0xffffffffu, excl, o);
        if (lane >= o) excl += t;
    }
    int wtot = __shfl_sync(0xffffffffu, excl, 31);
    excl -= cntl;
    if (lane == 31) s_w[wid] = wtot;
    __syncthreads();
    if (tid < 8) {
        int t = s_w[tid];
        int e = t;
#pragma unroll
        for (int o = 1; o < 8; o <<= 1) {
            int u = __shfl_up_sync(0xffu, e, o);
            if (tid >= o) e += u;
        }
        s_w[tid] = e - t;
        if (tid == 7) g_cnt[row] = min(e, MAXDEG);
    }
    __syncthreads();
    int off = s_w[wid] + excl;
    int* dst = g_col + row * MAXDEG;
    int col0 = tid * 32;
#pragma unroll
    for (int i = 0; i < 8; i++) {
        int c = col0 + i * 4;
        if (v[i].x) { if (off < MAXDEG) dst[off] = c + 0; off++; }
        if (v[i].y) { if (off < MAXDEG) dst[off] = c + 1; off++; }
        if (v[i].z) { if (off < MAXDEG) dst[off] = c + 2; off++; }
        if (v[i].w) { if (off < MAXDEG) dst[off] = c + 3; off++; }
    }
}

/* ========= SGEMM: 128x128 tile, BK=16, 8x8/thr, double-buffered ========= */
template <int DUAL>
__global__ __launch_bounds__(256) void sgemm128db(const float* __restrict__ A,
                                                  const float* __restrict__ B,
                                                  float* __restrict__ C,
                                                  __half* __restrict__ Ch,
                                                  int N, int K) {
    __shared__ __align__(16) float As[2][16][128];
    __shared__ __align__(16) float Bs[2][16][128];
    const int tid = threadIdx.x;
    const int tx = tid & 15, ty = tid >> 4;
    const int bn = (blockIdx.x & 1) * 128;
    const int bm = (blockIdx.x >> 1) * 128;
    const int aRow = tid >> 1, aCol = (tid & 1) * 8;
    const int bRow = tid >> 4, bCol = (tid & 15) * 8;
    float acc[8][8] = {};

    {
        const float* Ag = A + (size_t)(bm + aRow) * K + aCol;
        float4 a0 = *(const float4*)(Ag);
        float4 a1 = *(const float4*)(Ag + 4);
        As[0][aCol + 0][aRow] = a0.x; As[0][aCol + 1][aRow] = a0.y;
        As[0][aCol + 2][aRow] = a0.z; As[0][aCol + 3][aRow] = a0.w;
        As[0][aCol + 4][aRow] = a1.x; As[0][aCol + 5][aRow] = a1.y;
        As[0][aCol + 6][aRow] = a1.z; As[0][aCol + 7][aRow] = a1.w;
        const float* Bg = B + (size_t)bRow * N + bn + bCol;
        *(float4*)&Bs[0][bRow][bCol]     = *(const float4*)(Bg);
        *(float4*)&Bs[0][bRow][bCol + 4] = *(const float4*)(Bg + 4);
    }
    __syncthreads();

    int buf = 0;
    for (int k0 = 0; k0 < K; k0 += 16) {
        float4 na0, na1, nb0, nb1;
        const bool more = (k0 + 16 < K);
        if (more) {
            const float* Ag = A + (size_t)(bm + aRow) * K + k0 + 16 + aCol;
            na0 = *(const float4*)(Ag);
            na1 = *(const float4*)(Ag + 4);
            const float* Bg = B + (size_t)(k0 + 16 + bRow) * N + bn + bCol;
            nb0 = *(const float4*)(Bg);
            nb1 = *(const float4*)(Bg + 4);
        }
#pragma unroll
        for (int k = 0; k < 16; k++) {
            float4 ra0 = *(float4*)&As[buf][k][ty * 8];
            float4 ra1 = *(float4*)&As[buf][k][ty * 8 + 4];
            float4 rb0 = *(float4*)&Bs[buf][k][tx * 8];
            float4 rb1 = *(float4*)&Bs[buf][k][tx * 8 + 4];
            float ra[8] = {ra0.x, ra0.y, ra0.z, ra0.w, ra1.x, ra1.y, ra1.z, ra1.w};
            float rb[8] = {rb0.x, rb0.y, rb0.z, rb0.w, rb1.x, rb1.y, rb1.z, rb1.w};
#pragma unroll
            for (int i = 0; i < 8; i++)
#pragma unroll
                for (int j = 0; j < 8; j++) acc[i][j] += ra[i] * rb[j];
        }
        if (more) {
            int nb = buf ^ 1;
            As[nb][aCol + 0][aRow] = na0.x; As[nb][aCol + 1][aRow] = na0.y;
            As[nb][aCol + 2][aRow] = na0.z; As[nb][aCol + 3][aRow] = na0.w;
            As[nb][aCol + 4][aRow] = na1.x; As[nb][aCol + 5][aRow] = na1.y;
            As[nb][aCol + 6][aRow] = na1.z; As[nb][aCol + 7][aRow] = na1.w;
            *(float4*)&Bs[nb][bRow][bCol]     = nb0;
            *(float4*)&Bs[nb][bRow][bCol + 4] = nb1;
            __syncthreads();
            buf = nb;
        }
    }
#pragma unroll
    for (int i = 0; i < 8; i++) {
        int r = bm + ty * 8 + i, c = bn + tx * 8;
        float* crow = C + (size_t)r * N + c;
        *(float4*)(crow)     = make_float4(acc[i][0], acc[i][1], acc[i][2], acc[i][3]);
        *(float4*)(crow + 4) = make_float4(acc[i][4], acc[i][5], acc[i][6], acc[i][7]);
        if (DUAL) {
            __half2* h2 = (__half2*)(Ch + (size_t)r * N + c);
            h2[0] = __floats2half2_rn(acc[i][0], acc[i][1]);
            h2[1] = __floats2half2_rn(acc[i][2], acc[i][3]);
            h2[2] = __floats2half2_rn(acc[i][4], acc[i][5]);
            h2[3] = __floats2half2_rn(acc[i][6], acc[i][7]);
        }
    }
}

/* ------- K2: h1 = relu(adj@XW + b1); 4 rows/block, MLP=8 ------- */
__global__ __launch_bounds__(256) void spmm_relu(const float* __restrict__ b1,
                                                 float* __restrict__ out_cat) {
    const int tid = threadIdx.x;
    const int rl = tid >> 6;
    const int l64 = tid & 63;
    const int row = blockIdx.x * 4 + rl;
    __shared__ __align__(16) int s_col[4][MAXDEG];
    const int cnt = g_cnt[row];
    for (int j = l64; j < cnt; j += 64) s_col[rl][j] = g_col[row * MAXDEG + j];
    __syncthreads();
    const int ch = l64 * 4;
    float4 aa[8];
#pragma unroll
    for (int i = 0; i < 8; i++) aa[i] = make_float4(0.f, 0.f, 0.f, 0.f);
    int j = 0;
    for (; j + 8 <= cnt; j += 8) {
#pragma unroll
        for (int u = 0; u < 8; u++) {
            float4 v = *(const float4*)(g_XW + (size_t)s_col[rl][j + u] * NHID + ch);
            aa[u].x += v.x; aa[u].y += v.y; aa[u].z += v.z; aa[u].w += v.w;
        }
    }
    for (; j < cnt; j++) {
        float4 v = *(const float4*)(g_XW + (size_t)s_col[rl][j] * NHID + ch);
        aa[0].x += v.x; aa[0].y += v.y; aa[0].z += v.z; aa[0].w += v.w;
    }
    float4 acc = make_float4(0.f, 0.f, 0.f, 0.f);
#pragma unroll
    for (int i = 0; i < 8; i++) {
        acc.x += aa[i].x; acc.y += aa[i].y; acc.z += aa[i].z; acc.w += aa[i].w;
    }
    float4 bb = *(const float4*)(b1 + ch);
    float4 h = make_float4(fmaxf(acc.x + bb.x, 0.f), fmaxf(acc.y + bb.y, 0.f),
                           fmaxf(acc.z + bb.z, 0.f), fmaxf(acc.w + bb.w, 0.f));
    *(float4*)(g_h1 + (size_t)row * NHID + ch) = h;
    *(float4*)(out_cat + (size_t)row * CATW + ch) = h;
}

/* ---------------- K4: f1 = Wh@a[:H], f2 = Wh@a[H:] (fp32 Wh) ------------- */
__global__ __launch_bounds__(256) void compute_f(const float* __restrict__ a_vec) {
    int lane = threadIdx.x & 31, wid = threadIdx.x >> 5;
    int row  = blockIdx.x * 8 + wid;
    float a1 = 0.f, a2 = 0.f;
    const float* wh = g_Wh32 + (size_t)row * NHID;
#pragma unroll
    for (int k = lane; k < NHID; k += 32) {
        float w = wh[k];
        a1 += w * a_vec[k];
        a2 += w * a_vec[NHID + k];
    }
#pragma unroll
    for (int o = 16; o; o >>= 1) {
        a1 += __shfl_down_sync(0xffffffffu, a1, o);
        a2 += __shfl_down_sync(0xffffffffu, a2, o);
    }
    if (lane == 0) { g_f1[row] = a1; g_f2[row] = a2; }
}

/* -- K5: softmax + sparse scatter into pre-zeroed att + h' + elu + aW3 ---- */
__global__ __launch_bounds__(256) void attn_kernel(float* __restrict__ att_out,
                                                   const float* __restrict__ W3) {
    const int row = blockIdx.x, tid = threadIdx.x;
    const int lane = tid & 31, wid = tid >> 5;
    __shared__ __align__(16) int   s_col[MAXDEG];
    __shared__ __align__(16) float s_att[MAXDEG];
    __shared__ __align__(16) float s_red[8];
    __shared__ __align__(16) float s_a[NHID];
    __shared__ __align__(16) float s_p[256];
    __shared__ float s_m, s_Z;
    const int cnt = g_cnt[row];
    int col = 0;
    if (tid < cnt) { col = g_col[row * MAXDEG + tid]; s_col[tid] = col; }
    const float f1 = g_f1[row];
    float e = -INFINITY;
    if (tid < cnt) {
        float t = f1 + g_f2[col];
        e = (t > 0.f) ? t : ALPHAC * t;
    }
    float wm = e;
#pragma unroll
    for (int o = 16; o; o >>= 1) wm = fmaxf(wm, __shfl_xor_sync(0xffffffffu, wm, o));
    if (lane == 0) s_red[wid] = wm;
    __syncthreads();
    if (tid == 0) {
        float m = s_red[0];
#pragma unroll
        for (int i = 1; i < 8; i++) m = fmaxf(m, s_red[i]);
        s_m = m;
    }
    __syncthreads();
    float w = (tid < cnt) ? __expf(e - s_m) : 0.f;
    float ws = w;
#pragma unroll
    for (int o = 16; o; o >>= 1) ws += __shfl_xor_sync(0xffffffffu, ws, o);
    if (lane == 0) s_red[wid] = ws;
    __syncthreads();
    if (tid == 0) {
        float z = 0.f;
#pragma unroll
        for (int i = 0; i < 8; i++) z += s_red[i];
        s_Z = z;
    }
    __syncthreads();
    const float inv_Z = 1.f / s_Z;
    if (tid < cnt) {
        float att = w * inv_Z;
        s_att[tid] = att;
        att_out[(size_t)row * Nn + col] = att;   /* scatter into zeroed row */
    }
    __syncthreads();
    float acc0 = 0.f, acc1 = 0.f;
    int j = 0;
    for (; j + 4 <= cnt; j += 4) {
        acc0 += s_att[j]     * __half2float(g_Whh[(size_t)s_col[j]     * NHID + tid]);
        acc1 += s_att[j + 1] * __half2float(g_Whh[(size_t)s_col[j + 1] * NHID + tid]);
        acc0 += s_att[j + 2] * __half2float(g_Whh[(size_t)s_col[j + 2] * NHID + tid]);
        acc1 += s_att[j + 3] * __half2float(g_Whh[(size_t)s_col[j + 3] * NHID + tid]);
    }
    for (; j < cnt; j++)
        acc0 += s_att[j] * __half2float(g_Whh[(size_t)s_col[j] * NHID + tid]);
    float acc = acc0 + acc1;
    float a = (acc > 0.f) ? acc : expm1f(acc);          /* elu */
    s_a[tid] = a;
    __syncthreads();
    int c = tid >> 4, kk = tid & 15;
    float p = 0.f;
    for (int k = kk; k < NHID; k += 16) p += s_a[k] * W3[k * NCLASS + c];
    s_p[tid] = p;
    __syncthreads();
    if (tid < NCLASS) {
        float s = 0.f;
#pragma unroll
        for (int k = 0; k < 16; k++) s += s_p[tid * 16 + k];
        g_aW3[(size_t)row * NCLASS + tid] = s;
    }
}

/* ---------------- K6: out = adj@aW3 + b3; sigmoid + concat tail ---------- */
__global__ __launch_bounds__(128) void gc3_kernel(const float* __restrict__ b3,
                                                  float* __restrict__ sig_out,
                                                  float* __restrict__ out_cat) {
    int tid = threadIdx.x;
    int r = blockIdx.x * 8 + (tid >> 4);
    int c = tid & 15;
    int cnt = g_cnt[r];
    const int* cols = g_col + r * MAXDEG;
    float acc = 0.f;
    for (int j = 0; j < cnt; j++)
        acc += g_aW3[(size_t)cols[j] * NCLASS + c];
    float o = acc + b3[c];
    sig_out[(size_t)r * NCLASS + c] = 1.f / (1.f + __expf(-o));
    out_cat[(size_t)r * CATW + NHID + c] = o;
}

/* ---- launch: R8 fork, memset split across streams to balance window 1 --- */
extern "C" void kernel_launch(void* const* d_in, const int* in_sizes, int n_in,
                              void* d_out, int out_size) {
    const float* x     = (const float*)d_in[0];
    const int*   adj   = (const int*)  d_in[1];
    const float* W1    = (const float*)d_in[2];
    const float* b1    = (const float*)d_in[3];
    const float* Wa    = (const float*)d_in[4];
    const float* a_vec = (const float*)d_in[5];
    const float* W3    = (const float*)d_in[6];
    const float* b3    = (const float*)d_in[7];

    float* out = (float*)d_out;
    float* sig = out;
    float* att = out + (size_t)Nn * NCLASS;
    float* cat = att + (size_t)Nn * Nn;

    float *pXW, *pH1, *pWh32;
    __half* pWhh;
    cudaGetSymbolAddress((void**)&pXW, g_XW);
    cudaGetSymbolAddress((void**)&pH1, g_h1);
    cudaGetSymbolAddress((void**)&pWh32, g_Wh32);
    cudaGetSymbolAddress((void**)&pWhh, g_Whh);

    static cudaStream_t s2 = nullptr;
    static cudaEvent_t ev_fork = nullptr, ev_side = nullptr;
    if (s2 == nullptr) {
        cudaStreamCreateWithFlags(&s2, cudaStreamNonBlocking);
        cudaEventCreateWithFlags(&ev_fork, cudaEventDisableTiming);
        cudaEventCreateWithFlags(&ev_side, cudaEventDisableTiming);
    }

    /* memset split: main zeroes first 2731 rows (~12us), side zeroes the
       rest (~22us) then builds CSR (~40us); main then runs gemm1 (~50us).
       Balanced window: main 12+50=62 vs side 22+40=62 (was 0+50 vs 34+40). */
    const size_t MS_MAIN = (size_t)2731 * Nn * sizeof(float);
    const size_t MS_ALL  = (size_t)Nn * Nn * sizeof(float);

    cudaEventRecord(ev_fork, 0);
    cudaStreamWaitEvent(s2, ev_fork, 0);
    cudaMemsetAsync((char*)att + MS_MAIN, 0, MS_ALL - MS_MAIN, s2);
    build_csr<<<Nn, 256, 0, s2>>>((const int4*)adj);
    cudaEventRecord(ev_side, s2);

    cudaMemsetAsync(att, 0, MS_MAIN, 0);
    sgemm128db<0><<<(NHID / 128) * (Nn / 128), 256>>>(x, W1, pXW, nullptr,
                                                      NHID, NFEATC);
    cudaStreamWaitEvent(0, ev_side, 0);   /* join before spmm needs CSR */

    spmm_relu<<<Nn / 4, 256>>>(b1, cat);

    sgemm128db<1><<<(NHID / 128) * (Nn / 128), 256>>>(pH1, Wa, pWh32, pWhh,
                                                      NHID, NHID);

    compute_f<<<Nn / 8, 256>>>(a_vec);

    attn_kernel<<<Nn, 256>>>(att, W3);

    gc3_kernel<<<Nn / 8, 128>>>(b3, sig, cat);
}

// round 16
// speedup vs baseline: 1.2233x; 1.2233x over previous
#include <cuda_runtime.h>
#include <cuda_fp16.h>
#include <math.h>
#include <stdint.h>

#define Nn      8192
#define NFEATC  512
#define NHID    256
#define NCLASS  16
#define MAXDEG  160
#define ALPHAC  0.01f
#define CATW    (NHID + NCLASS)   /* 272 */

/* ---------------- device scratch ---------------- */
__device__ int    g_col[Nn * MAXDEG];
__device__ int    g_cnt[Nn];
__device__ float  g_XW[Nn * NHID];
__device__ float  g_h1[Nn * NHID];
__device__ float  g_Wh32[Nn * NHID];
__device__ __half g_Whh[Nn * NHID];
__device__ float  g_f1[Nn];
__device__ float  g_f2[Nn];
__device__ float  g_aW3[Nn * NCLASS];

/* ------ K1: CSR build, thread t owns cols [32t,32t+32), ONE block scan --- */
__global__ __launch_bounds__(256) void build_csr(const int4* __restrict__ adj4) {
    const int row = blockIdx.x, tid = threadIdx.x;
    const int lane = tid & 31, wid = tid >> 5;
    __shared__ __align__(16) int s_w[8];
    int4 v[8];
    const int4* base = adj4 + (size_t)row * (Nn / 4) + tid * 8;
#pragma unroll
    for (int i = 0; i < 8; i++) v[i] = base[i];           /* MLP = 8 */
    int cntl = 0;
#pragma unroll
    for (int i = 0; i < 8; i++)
        cntl += (v[i].x != 0) + (v[i].y != 0) + (v[i].z != 0) + (v[i].w != 0);
    int excl = cntl;
#pragma unroll
    for (int o = 1; o < 32; o <<= 1) {
        int t = __shfl_up_sync(0xffffffffu, excl, o);
        if (lane >= o) excl += t;
    }
    int wtot = __shfl_sync(0xffffffffu, excl, 31);
    excl -= cntl;
    if (lane == 31) s_w[wid] = wtot;
    __syncthreads();
    if (tid < 8) {
        int t = s_w[tid];
        int e = t;
#pragma unroll
        for (int o = 1; o < 8; o <<= 1) {
            int u = __shfl_up_sync(0xffu, e, o);
            if (tid >= o) e += u;
        }
        s_w[tid] = e - t;
        if (tid == 7) g_cnt[row] = min(e, MAXDEG);
    }
    __syncthreads();
    int off = s_w[wid] + excl;
    int* dst = g_col + row * MAXDEG;
    int col0 = tid * 32;
#pragma unroll
    for (int i = 0; i < 8; i++) {
        int c = col0 + i * 4;
        if (v[i].x) { if (off < MAXDEG) dst[off] = c + 0; off++; }
        if (v[i].y) { if (off < MAXDEG) dst[off] = c + 1; off++; }
        if (v[i].z) { if (off < MAXDEG) dst[off] = c + 2; off++; }
        if (v[i].w) { if (off < MAXDEG) dst[off] = c + 3; off++; }
    }
}

/* ========= SGEMM: 128x128 tile, BK=16, 8x8/thr, double-buffered ========= */
template <int DUAL>
__global__ __launch_bounds__(256) void sgemm128db(const float* __restrict__ A,
                                                  const float* __restrict__ B,
                                                  float* __restrict__ C,
                                                  __half* __restrict__ Ch,
                                                  int N, int K) {
    __shared__ __align__(16) float As[2][16][128];
    __shared__ __align__(16) float Bs[2][16][128];
    const int tid = threadIdx.x;
    const int tx = tid & 15, ty = tid >> 4;
    const int bn = (blockIdx.x & 1) * 128;
    const int bm = (blockIdx.x >> 1) * 128;
    const int aRow = tid >> 1, aCol = (tid & 1) * 8;
    const int bRow = tid >> 4, bCol = (tid & 15) * 8;
    float acc[8][8] = {};

    {
        const float* Ag = A + (size_t)(bm + aRow) * K + aCol;
        float4 a0 = *(const float4*)(Ag);
        float4 a1 = *(const float4*)(Ag + 4);
        As[0][aCol + 0][aRow] = a0.x; As[0][aCol + 1][aRow] = a0.y;
        As[0][aCol + 2][aRow] = a0.z; As[0][aCol + 3][aRow] = a0.w;
        As[0][aCol + 4][aRow] = a1.x; As[0][aCol + 5][aRow] = a1.y;
        As[0][aCol + 6][aRow] = a1.z; As[0][aCol + 7][aRow] = a1.w;
        const float* Bg = B + (size_t)bRow * N + bn + bCol;
        *(float4*)&Bs[0][bRow][bCol]     = *(const float4*)(Bg);
        *(float4*)&Bs[0][bRow][bCol + 4] = *(const float4*)(Bg + 4);
    }
    __syncthreads();

    int buf = 0;
    for (int k0 = 0; k0 < K; k0 += 16) {
        float4 na0, na1, nb0, nb1;
        const bool more = (k0 + 16 < K);
        if (more) {
            const float* Ag = A + (size_t)(bm + aRow) * K + k0 + 16 + aCol;
            na0 = *(const float4*)(Ag);
            na1 = *(const float4*)(Ag + 4);
            const float* Bg = B + (size_t)(k0 + 16 + bRow) * N + bn + bCol;
            nb0 = *(const float4*)(Bg);
            nb1 = *(const float4*)(Bg + 4);
        }
#pragma unroll
        for (int k = 0; k < 16; k++) {
            float4 ra0 = *(float4*)&As[buf][k][ty * 8];
            float4 ra1 = *(float4*)&As[buf][k][ty * 8 + 4];
            float4 rb0 = *(float4*)&Bs[buf][k][tx * 8];
            float4 rb1 = *(float4*)&Bs[buf][k][tx * 8 + 4];
            float ra[8] = {ra0.x, ra0.y, ra0.z, ra0.w, ra1.x, ra1.y, ra1.z, ra1.w};
            float rb[8] = {rb0.x, rb0.y, rb0.z, rb0.w, rb1.x, rb1.y, rb1.z, rb1.w};
#pragma unroll
            for (int i = 0; i < 8; i++)
#pragma unroll
                for (int j = 0; j < 8; j++) acc[i][j] += ra[i] * rb[j];
        }
        if (more) {
            int nb = buf ^ 1;
            As[nb][aCol + 0][aRow] = na0.x; As[nb][aCol + 1][aRow] = na0.y;
            As[nb][aCol + 2][aRow] = na0.z; As[nb][aCol + 3][aRow] = na0.w;
            As[nb][aCol + 4][aRow] = na1.x; As[nb][aCol + 5][aRow] = na1.y;
            As[nb][aCol + 6][aRow] = na1.z; As[nb][aCol + 7][aRow] = na1.w;
            *(float4*)&Bs[nb][bRow][bCol]     = nb0;
            *(float4*)&Bs[nb][bRow][bCol + 4] = nb1;
            __syncthreads();
            buf = nb;
        }
    }
#pragma unroll
    for (int i = 0; i < 8; i++) {
        int r = bm + ty * 8 + i, c = bn + tx * 8;
        float* crow = C + (size_t)r * N + c;
        *(float4*)(crow)     = make_float4(acc[i][0], acc[i][1], acc[i][2], acc[i][3]);
        *(float4*)(crow + 4) = make_float4(acc[i][4], acc[i][5], acc[i][6], acc[i][7]);
        if (DUAL) {
            __half2* h2 = (__half2*)(Ch + (size_t)r * N + c);
            h2[0] = __floats2half2_rn(acc[i][0], acc[i][1]);
            h2[1] = __floats2half2_rn(acc[i][2], acc[i][3]);
            h2[2] = __floats2half2_rn(acc[i][4], acc[i][5]);
            h2[3] = __floats2half2_rn(acc[i][6], acc[i][7]);
        }
    }
}

/* ------- K2: h1 = relu(adj@XW + b1); 4 rows/block, MLP=8 ------- */
__global__ __launch_bounds__(256) void spmm_relu(const float* __restrict__ b1,
                                                 float* __restrict__ out_cat) {
    const int tid = threadIdx.x;
    const int rl = tid >> 6;
    const int l64 = tid & 63;
    const int row = blockIdx.x * 4 + rl;
    __shared__ __align__(16) int s_col[4][MAXDEG];
    const int cnt = g_cnt[row];
    for (int j = l64; j < cnt; j += 64) s_col[rl][j] = g_col[row * MAXDEG + j];
    __syncthreads();
    const int ch = l64 * 4;
    float4 aa[8];
#pragma unroll
    for (int i = 0; i < 8; i++) aa[i] = make_float4(0.f, 0.f, 0.f, 0.f);
    int j = 0;
    for (; j + 8 <= cnt; j += 8) {
#pragma unroll
        for (int u = 0; u < 8; u++) {
            float4 v = *(const float4*)(g_XW + (size_t)s_col[rl][j + u] * NHID + ch);
            aa[u].x += v.x; aa[u].y += v.y; aa[u].z += v.z; aa[u].w += v.w;
        }
    }
    for (; j < cnt; j++) {
        float4 v = *(const float4*)(g_XW + (size_t)s_col[rl][j] * NHID + ch);
        aa[0].x += v.x; aa[0].y += v.y; aa[0].z += v.z; aa[0].w += v.w;
    }
    float4 acc = make_float4(0.f, 0.f, 0.f, 0.f);
#pragma unroll
    for (int i = 0; i < 8; i++) {
        acc.x += aa[i].x; acc.y += aa[i].y; acc.z += aa[i].z; acc.w += aa[i].w;
    }
    float4 bb = *(const float4*)(b1 + ch);
    float4 h = make_float4(fmaxf(acc.x + bb.x, 0.f), fmaxf(acc.y + bb.y, 0.f),
                           fmaxf(acc.z + bb.z, 0.f), fmaxf(acc.w + bb.w, 0.f));
    *(float4*)(g_h1 + (size_t)row * NHID + ch) = h;
    *(float4*)(out_cat + (size_t)row * CATW + ch) = h;
}

/* ---------------- K4: f1 = Wh@a[:H], f2 = Wh@a[H:] (fp32 Wh) ------------- */
__global__ __launch_bounds__(256) void compute_f(const float* __restrict__ a_vec) {
    int lane = threadIdx.x & 31, wid = threadIdx.x >> 5;
    int row  = blockIdx.x * 8 + wid;
    float a1 = 0.f, a2 = 0.f;
    const float* wh = g_Wh32 + (size_t)row * NHID;
#pragma unroll
    for (int k = lane; k < NHID; k += 32) {
        float w = wh[k];
        a1 += w * a_vec[k];
        a2 += w * a_vec[NHID + k];
    }
#pragma unroll
    for (int o = 16; o; o >>= 1) {
        a1 += __shfl_down_sync(0xffffffffu, a1, o);
        a2 += __shfl_down_sync(0xffffffffu, a2, o);
    }
    if (lane == 0) { g_f1[row] = a1; g_f2[row] = a2; }
}

/* -- K5: softmax + sparse scatter into pre-zeroed att + h' + elu + aW3 ---- */
__global__ __launch_bounds__(256) void attn_kernel(float* __restrict__ att_out,
                                                   const float* __restrict__ W3) {
    const int row = blockIdx.x, tid = threadIdx.x;
    const int lane = tid & 31, wid = tid >> 5;
    __shared__ __align__(16) int   s_col[MAXDEG];
    __shared__ __align__(16) float s_att[MAXDEG];
    __shared__ __align__(16) float s_red[8];
    __shared__ __align__(16) float s_a[NHID];
    __shared__ __align__(16) float s_p[256];
    __shared__ float s_m, s_Z;
    const int cnt = g_cnt[row];
    int col = 0;
    if (tid < cnt) { col = g_col[row * MAXDEG + tid]; s_col[tid] = col; }
    const float f1 = g_f1[row];
    float e = -INFINITY;
    if (tid < cnt) {
        float t = f1 + g_f2[col];
        e = (t > 0.f) ? t : ALPHAC * t;
    }
    float wm = e;
#pragma unroll
    for (int o = 16; o; o >>= 1) wm = fmaxf(wm, __shfl_xor_sync(0xffffffffu, wm, o));
    if (lane == 0) s_red[wid] = wm;
    __syncthreads();
    if (tid == 0) {
        float m = s_red[0];
#pragma unroll
        for (int i = 1; i < 8; i++) m = fmaxf(m, s_red[i]);
        s_m = m;
    }
    __syncthreads();
    float w = (tid < cnt) ? __expf(e - s_m) : 0.f;
    float ws = w;
#pragma unroll
    for (int o = 16; o; o >>= 1) ws += __shfl_xor_sync(0xffffffffu, ws, o);
    if (lane == 0) s_red[wid] = ws;
    __syncthreads();
    if (tid == 0) {
        float z = 0.f;
#pragma unroll
        for (int i = 0; i < 8; i++) z += s_red[i];
        s_Z = z;
    }
    __syncthreads();
    const float inv_Z = 1.f / s_Z;
    if (tid < cnt) {
        float att = w * inv_Z;
        s_att[tid] = att;
        att_out[(size_t)row * Nn + col] = att;   /* scatter into zeroed row */
    }
    __syncthreads();
    float acc0 = 0.f, acc1 = 0.f;
    int j = 0;
    for (; j + 4 <= cnt; j += 4) {
        acc0 += s_att[j]     * __half2float(g_Whh[(size_t)s_col[j]     * NHID + tid]);
        acc1 += s_att[j + 1] * __half2float(g_Whh[(size_t)s_col[j + 1] * NHID + tid]);
        acc0 += s_att[j + 2] * __half2float(g_Whh[(size_t)s_col[j + 2] * NHID + tid]);
        acc1 += s_att[j + 3] * __half2float(g_Whh[(size_t)s_col[j + 3] * NHID + tid]);
    }
    for (; j < cnt; j++)
        acc0 += s_att[j] * __half2float(g_Whh[(size_t)s_col[j] * NHID + tid]);
    float acc = acc0 + acc1;
    float a = (acc > 0.f) ? acc : expm1f(acc);          /* elu */
    s_a[tid] = a;
    __syncthreads();
    int c = tid >> 4, kk = tid & 15;
    float p = 0.f;
    for (int k = kk; k < NHID; k += 16) p += s_a[k] * W3[k * NCLASS + c];
    s_p[tid] = p;
    __syncthreads();
    if (tid < NCLASS) {
        float s = 0.f;
#pragma unroll
        for (int k = 0; k < 16; k++) s += s_p[tid * 16 + k];
        g_aW3[(size_t)row * NCLASS + tid] = s;
    }
}

/* ---------------- K6: out = adj@aW3 + b3; sigmoid + concat tail ---------- */
__global__ __launch_bounds__(128) void gc3_kernel(const float* __restrict__ b3,
                                                  float* __restrict__ sig_out,
                                                  float* __restrict__ out_cat) {
    int tid = threadIdx.x;
    int r = blockIdx.x * 8 + (tid >> 4);
    int c = tid & 15;
    int cnt = g_cnt[r];
    const int* cols = g_col + r * MAXDEG;
    float acc = 0.f;
    for (int j = 0; j < cnt; j++)
        acc += g_aW3[(size_t)cols[j] * NCLASS + c];
    float o = acc + b3[c];
    sig_out[(size_t)r * NCLASS + c] = 1.f / (1.f + __expf(-o));
    out_cat[(size_t)r * CATW + NHID + c] = o;
}

/* ---------------- launch: single fork (DRAM work ∥ gemm1) ---------------- */
extern "C" void kernel_launch(void* const* d_in, const int* in_sizes, int n_in,
                              void* d_out, int out_size) {
    const float* x     = (const float*)d_in[0];
    const int*   adj   = (const int*)  d_in[1];
    const float* W1    = (const float*)d_in[2];
    const float* b1    = (const float*)d_in[3];
    const float* Wa    = (const float*)d_in[4];
    const float* a_vec = (const float*)d_in[5];
    const float* W3    = (const float*)d_in[6];
    const float* b3    = (const float*)d_in[7];

    float* out = (float*)d_out;
    float* sig = out;
    float* att = out + (size_t)Nn * NCLASS;
    float* cat = att + (size_t)Nn * Nn;

    float *pXW, *pH1, *pWh32;
    __half* pWhh;
    cudaGetSymbolAddress((void**)&pXW, g_XW);
    cudaGetSymbolAddress((void**)&pH1, g_h1);
    cudaGetSymbolAddress((void**)&pWh32, g_Wh32);
    cudaGetSymbolAddress((void**)&pWhh, g_Whh);

    static cudaStream_t s2 = nullptr;
    static cudaEvent_t ev_fork = nullptr, ev_side = nullptr;
    if (s2 == nullptr) {
        cudaStreamCreateWithFlags(&s2, cudaStreamNonBlocking);
        cudaEventCreateWithFlags(&ev_fork, cudaEventDisableTiming);
        cudaEventCreateWithFlags(&ev_side, cudaEventDisableTiming);
    }

    /* side stream: pure DRAM work (268MB memset + 268MB adj read)       */
    /* main stream: gemm1 (fma-bound). Disjoint resources -> overlap.    */
    cudaEventRecord(ev_fork, 0);
    cudaStreamWaitEvent(s2, ev_fork, 0);
    cudaMemsetAsync(att, 0, (size_t)Nn * Nn * sizeof(float), s2);
    build_csr<<<Nn, 256, 0, s2>>>((const int4*)adj);
    cudaEventRecord(ev_side, s2);

    sgemm128db<0><<<(NHID / 128) * (Nn / 128), 256>>>(x, W1, pXW, nullptr,
                                                      NHID, NFEATC);
    cudaStreamWaitEvent(0, ev_side, 0);   /* join before spmm needs CSR */

    spmm_relu<<<Nn / 4, 256>>>(b1, cat);

    sgemm128db<1><<<(NHID / 128) * (Nn / 128), 256>>>(pH1, Wa, pWh32, pWhh,
                                                      NHID, NHID);

    compute_f<<<Nn / 8, 256>>>(a_vec);

    attn_kernel<<<Nn, 256>>>(att, W3);

    gc3_kernel<<<Nn / 8, 128>>>(b3, sig, cat);
}